// round 11
// baseline (speedup 1.0000x reference)
#include <cuda_runtime.h>
#include <cuda_bf16.h>

// Collapsed forward (linear in context_batch -> batch reduces to 2 scalars):
//   u_i = r_i @ Wv   (r0,r1 = rows of ctx_w, r2 = ctx_b; u2 += bv)
//   w_i = u_i @ Wo   (w2 += bo)
//   P_i[s,h] = w_i @ Whead[s,h]  (+bias)
//   out[h,b,:] = c0[b]*P0 + c1[b]*P1 + P2  (selected by sid[b])
//
// R9: NO cross-cluster sync at all. 8 independent clusters of 8 CTAs; each
// cluster redundantly computes the full u and w vectors (redundant reads are
// L2-deduped), shares slices via per-cluster scratch + HW cluster barriers
// (~380cyc, contention-free). Wo/Wh slices are prefetch.global.L2-warmed at
// kernel start so stage B/C loads are L2 hits. 512 thr/CTA, 16 independent
// float4 loads per thread per stage (high MLP).

#define D_MODEL 512
#define NB 16
#define NOUT 64
#define NBLK 64          // 8 clusters x 8 CTAs

__device__ float g_u[8][3][D_MODEL];     // per-cluster u vectors
__device__ float g_w[8][3][D_MODEL];     // per-cluster w vectors
__device__ float g_ph[8][8][3][NOUT];    // per-cluster per-rank head partials

#define CLUSTER_SYNC_FENCED() do {                                   \
    __syncthreads();                                                 \
    __threadfence();                                                 \
    asm volatile("barrier.cluster.arrive.aligned;" ::: "memory");    \
    asm volatile("barrier.cluster.wait.aligned;"   ::: "memory");    \
    __threadfence();                                                 \
} while (0)

__global__ void __cluster_dims__(8, 1, 1) __launch_bounds__(512, 1)
hivemind_r9(
    const float* __restrict__ cb,      // (16,2)
    const int*   __restrict__ sid,     // (16,)
    const float* __restrict__ ctx_w,   // (2,512)
    const float* __restrict__ ctx_b,   // (512,)
    const float* __restrict__ Wv,      // (512,512)
    const float* __restrict__ bv,      // (512,)
    const float* __restrict__ Wo,      // (512,512)
    const float* __restrict__ bo,      // (512,)
    const float* __restrict__ pred_w,  // (4,512,64)
    const float* __restrict__ pred_b,  // (4,64)
    const float* __restrict__ act_w,   // (4,512,64)
    const float* __restrict__ act_b,   // (4,64)
    float* __restrict__ out)           // [pred(16x64), act(16x64)]
{
    __shared__ float s_x[3][D_MODEL];          // 6KB stage input vectors
    __shared__ float s_red[16][3][64];         // 12KB per-warp partials
    __shared__ float s_P[3][NOUT];
    __shared__ float s_cb[NB * 2];
    __shared__ int   s_sid[NB];

    const int blk  = blockIdx.x;
    const int t    = threadIdx.x;              // 512 threads
    const int cl   = blk >> 3;                 // cluster 0..7 = (s,h)
    const int r    = blk & 7;                  // rank in cluster
    const int q    = t & 15;                   // col quad 0..15 (4 cols each)
    const int ks   = t >> 4;                   // k-split 0..31
    const int w    = t >> 5;                   // warp 0..15
    const int lane = t & 31;

    const int sp = cl >> 1, h = cl & 1;
    const float* Wh = (h ? act_w : pred_w) + (size_t)sp * D_MODEL * NOUT;
    const float* bh = (h ? act_b : pred_b) + sp * NOUT;

    // ---- L2 prefetch for stages B and C (barrier-independent) -----------
    #pragma unroll
    for (int j = 0; j < 2; ++j) {              // Wo slice: 1024 lines, 2/thread
        const int l = t + j * 512;
        const float* p = &Wo[(size_t)(l >> 1) * D_MODEL + r * 64 + (l & 1) * 32];
        asm volatile("prefetch.global.L2 [%0];" :: "l"(p));
    }
    if (t < 128) {                             // Wh slice: 128 lines
        const float* p = &Wh[(size_t)(r * 64 + (t >> 1)) * NOUT + (t & 1) * 32];
        asm volatile("prefetch.global.L2 [%0];" :: "l"(p));
    }

    // ================= Stage A: u_i = r_i @ Wv ===========================
    s_x[0][t] = ctx_w[t];
    s_x[1][t] = ctx_w[D_MODEL + t];
    s_x[2][t] = ctx_b[t];
    if (t < NB * 2) s_cb[t]  = cb[t];
    if (t < NB)     s_sid[t] = sid[t];
    __syncthreads();
    {
        const int d0 = r * 64 + q * 4;
        float4 a0 = {0,0,0,0}, a1 = {0,0,0,0}, a2 = {0,0,0,0};
        #pragma unroll
        for (int i = 0; i < 16; ++i) {
            const int k = ks * 16 + i;
            const float4 wv = *(const float4*)&Wv[(size_t)k * D_MODEL + d0];
            const float x0 = s_x[0][k], x1 = s_x[1][k], x2 = s_x[2][k];
            a0.x = fmaf(x0, wv.x, a0.x); a0.y = fmaf(x0, wv.y, a0.y);
            a0.z = fmaf(x0, wv.z, a0.z); a0.w = fmaf(x0, wv.w, a0.w);
            a1.x = fmaf(x1, wv.x, a1.x); a1.y = fmaf(x1, wv.y, a1.y);
            a1.z = fmaf(x1, wv.z, a1.z); a1.w = fmaf(x1, wv.w, a1.w);
            a2.x = fmaf(x2, wv.x, a2.x); a2.y = fmaf(x2, wv.y, a2.y);
            a2.z = fmaf(x2, wv.z, a2.z); a2.w = fmaf(x2, wv.w, a2.w);
        }
        a0.x += __shfl_xor_sync(0xffffffffu, a0.x, 16);
        a0.y += __shfl_xor_sync(0xffffffffu, a0.y, 16);
        a0.z += __shfl_xor_sync(0xffffffffu, a0.z, 16);
        a0.w += __shfl_xor_sync(0xffffffffu, a0.w, 16);
        a1.x += __shfl_xor_sync(0xffffffffu, a1.x, 16);
        a1.y += __shfl_xor_sync(0xffffffffu, a1.y, 16);
        a1.z += __shfl_xor_sync(0xffffffffu, a1.z, 16);
        a1.w += __shfl_xor_sync(0xffffffffu, a1.w, 16);
        a2.x += __shfl_xor_sync(0xffffffffu, a2.x, 16);
        a2.y += __shfl_xor_sync(0xffffffffu, a2.y, 16);
        a2.z += __shfl_xor_sync(0xffffffffu, a2.z, 16);
        a2.w += __shfl_xor_sync(0xffffffffu, a2.w, 16);
        if (lane < 16) {
            *(float4*)&s_red[w][0][q * 4] = a0;
            *(float4*)&s_red[w][1][q * 4] = a1;
            *(float4*)&s_red[w][2][q * 4] = a2;
        }
    }
    __syncthreads();
    if (t < 192) {
        const int i = t >> 6, col = t & 63;
        float s = 0.f;
        #pragma unroll
        for (int j = 0; j < 16; ++j) s += s_red[j][i][col];
        if (i == 2) s += bv[r * 64 + col];
        g_u[cl][i][r * 64 + col] = s;
    }
    CLUSTER_SYNC_FENCED();

    // ================= Stage B: w_i = u_i @ Wo ===========================
    s_x[0][t] = g_u[cl][0][t];
    s_x[1][t] = g_u[cl][1][t];
    s_x[2][t] = g_u[cl][2][t];
    __syncthreads();
    {
        const int d0 = r * 64 + q * 4;
        float4 a0 = {0,0,0,0}, a1 = {0,0,0,0}, a2 = {0,0,0,0};
        #pragma unroll
        for (int i = 0; i < 16; ++i) {
            const int k = ks * 16 + i;
            const float4 wv = *(const float4*)&Wo[(size_t)k * D_MODEL + d0];
            const float x0 = s_x[0][k], x1 = s_x[1][k], x2 = s_x[2][k];
            a0.x = fmaf(x0, wv.x, a0.x); a0.y = fmaf(x0, wv.y, a0.y);
            a0.z = fmaf(x0, wv.z, a0.z); a0.w = fmaf(x0, wv.w, a0.w);
            a1.x = fmaf(x1, wv.x, a1.x); a1.y = fmaf(x1, wv.y, a1.y);
            a1.z = fmaf(x1, wv.z, a1.z); a1.w = fmaf(x1, wv.w, a1.w);
            a2.x = fmaf(x2, wv.x, a2.x); a2.y = fmaf(x2, wv.y, a2.y);
            a2.z = fmaf(x2, wv.z, a2.z); a2.w = fmaf(x2, wv.w, a2.w);
        }
        a0.x += __shfl_xor_sync(0xffffffffu, a0.x, 16);
        a0.y += __shfl_xor_sync(0xffffffffu, a0.y, 16);
        a0.z += __shfl_xor_sync(0xffffffffu, a0.z, 16);
        a0.w += __shfl_xor_sync(0xffffffffu, a0.w, 16);
        a1.x += __shfl_xor_sync(0xffffffffu, a1.x, 16);
        a1.y += __shfl_xor_sync(0xffffffffu, a1.y, 16);
        a1.z += __shfl_xor_sync(0xffffffffu, a1.z, 16);
        a1.w += __shfl_xor_sync(0xffffffffu, a1.w, 16);
        a2.x += __shfl_xor_sync(0xffffffffu, a2.x, 16);
        a2.y += __shfl_xor_sync(0xffffffffu, a2.y, 16);
        a2.z += __shfl_xor_sync(0xffffffffu, a2.z, 16);
        a2.w += __shfl_xor_sync(0xffffffffu, a2.w, 16);
        if (lane < 16) {
            *(float4*)&s_red[w][0][q * 4] = a0;
            *(float4*)&s_red[w][1][q * 4] = a1;
            *(float4*)&s_red[w][2][q * 4] = a2;
        }
    }
    __syncthreads();
    if (t < 192) {
        const int i = t >> 6, col = t & 63;
        float s = 0.f;
        #pragma unroll
        for (int j = 0; j < 16; ++j) s += s_red[j][i][col];
        if (i == 2) s += bo[r * 64 + col];
        g_w[cl][i][r * 64 + col] = s;
    }
    CLUSTER_SYNC_FENCED();

    // ================= Stage C: P_i = w_i @ Wh (rank k-slice) ============
    s_x[0][t] = g_w[cl][0][t];
    s_x[1][t] = g_w[cl][1][t];
    s_x[2][t] = g_w[cl][2][t];
    __syncthreads();
    {
        const int o0 = q * 4;
        float4 a0 = {0,0,0,0}, a1 = {0,0,0,0}, a2 = {0,0,0,0};
        #pragma unroll
        for (int i = 0; i < 2; ++i) {
            const int k = r * 64 + ks * 2 + i;
            const float4 wv = *(const float4*)&Wh[(size_t)k * NOUT + o0];
            const float x0 = s_x[0][k], x1 = s_x[1][k], x2 = s_x[2][k];
            a0.x = fmaf(x0, wv.x, a0.x); a0.y = fmaf(x0, wv.y, a0.y);
            a0.z = fmaf(x0, wv.z, a0.z); a0.w = fmaf(x0, wv.w, a0.w);
            a1.x = fmaf(x1, wv.x, a1.x); a1.y = fmaf(x1, wv.y, a1.y);
            a1.z = fmaf(x1, wv.z, a1.z); a1.w = fmaf(x1, wv.w, a1.w);
            a2.x = fmaf(x2, wv.x, a2.x); a2.y = fmaf(x2, wv.y, a2.y);
            a2.z = fmaf(x2, wv.z, a2.z); a2.w = fmaf(x2, wv.w, a2.w);
        }
        a0.x += __shfl_xor_sync(0xffffffffu, a0.x, 16);
        a0.y += __shfl_xor_sync(0xffffffffu, a0.y, 16);
        a0.z += __shfl_xor_sync(0xffffffffu, a0.z, 16);
        a0.w += __shfl_xor_sync(0xffffffffu, a0.w, 16);
        a1.x += __shfl_xor_sync(0xffffffffu, a1.x, 16);
        a1.y += __shfl_xor_sync(0xffffffffu, a1.y, 16);
        a1.z += __shfl_xor_sync(0xffffffffu, a1.z, 16);
        a1.w += __shfl_xor_sync(0xffffffffu, a1.w, 16);
        a2.x += __shfl_xor_sync(0xffffffffu, a2.x, 16);
        a2.y += __shfl_xor_sync(0xffffffffu, a2.y, 16);
        a2.z += __shfl_xor_sync(0xffffffffu, a2.z, 16);
        a2.w += __shfl_xor_sync(0xffffffffu, a2.w, 16);
        if (lane < 16) {
            *(float4*)&s_red[w][0][q * 4] = a0;
            *(float4*)&s_red[w][1][q * 4] = a1;
            *(float4*)&s_red[w][2][q * 4] = a2;
        }
    }
    __syncthreads();
    if (t < 192) {
        const int i = t >> 6, o = t & 63;
        float p = 0.f;
        #pragma unroll
        for (int j = 0; j < 16; ++j) p += s_red[j][i][o];
        g_ph[cl][r][i][o] = p;
    }
    CLUSTER_SYNC_FENCED();

    // ---- rank 0: combine 8 rank partials + batch output -----------------
    if (r != 0) return;
    if (t < 192) {
        const int i = t >> 6, o = t & 63;
        float p = 0.f;
        #pragma unroll
        for (int j = 0; j < 8; ++j) p += g_ph[cl][j][i][o];
        if (i == 2) p += bh[o];
        s_P[i][o] = p;
    }
    __syncthreads();
    if (t < NOUT) {
        const float p0 = s_P[0][t], p1 = s_P[1][t], p2 = s_P[2][t];
        #pragma unroll
        for (int b = 0; b < NB; ++b) {
            if (s_sid[b] == sp)
                out[h * NB * NOUT + b * NOUT + t] =
                    fmaf(s_cb[b * 2], p0, fmaf(s_cb[b * 2 + 1], p1, p2));
        }
    }
}

extern "C" void kernel_launch(void* const* d_in, const int* in_sizes, int n_in,
                              void* d_out, int out_size) {
    const float* cb     = (const float*)d_in[1];
    const int*   sid    = (const int*)  d_in[2];
    const float* ctx_w  = (const float*)d_in[16];
    const float* ctx_b  = (const float*)d_in[17];
    const float* ca_wv  = (const float*)d_in[22];
    const float* ca_bv  = (const float*)d_in[23];
    const float* ca_wo  = (const float*)d_in[24];
    const float* ca_bo  = (const float*)d_in[25];
    const float* pred_w = (const float*)d_in[26];
    const float* pred_b = (const float*)d_in[27];
    const float* act_w  = (const float*)d_in[28];
    const float* act_b  = (const float*)d_in[29];
    float* out = (float*)d_out;

    hivemind_r9<<<NBLK, 512>>>(cb, sid, ctx_w, ctx_b,
                               ca_wv, ca_bv, ca_wo, ca_bo,
                               pred_w, pred_b, act_w, act_b, out);
}